// round 4
// baseline (speedup 1.0000x reference)
#include <cuda_runtime.h>
#include <math.h>

#define NBATCH 256
#define LSRC   400
#define LATD   32
#define NT     38400
#define NA     38400
#define NBD    76800
#define NROWS  (NT + NA + NBD)

// ---------------- scratch (no allocs allowed) ----------------
__device__ float        g_q[(size_t)NROWS * LATD];
__device__ float        g_cxt[(size_t)NROWS * LATD];
__device__ int          g_order[NROWS];
__device__ int          g_hist[3 * 256];
__device__ int          g_cursor[3 * 256];
__device__ int          g_off[3 * 257];
__device__ double       g_loss[3];
__device__ unsigned int g_corr[3];

// ---------------- setup / sort kernels ----------------
__global__ void zero_kernel() {
    int t = blockIdx.x * blockDim.x + threadIdx.x;
    if (t < 3 * 256) { g_hist[t] = 0; g_cursor[t] = 0; }
    if (t < 3) { g_loss[t] = 0.0; g_corr[t] = 0u; }
}

__global__ void hist_kernel(const int* __restrict__ idx, int n, int head) {
    int i = blockIdx.x * blockDim.x + threadIdx.x;
    if (i < n) atomicAdd(&g_hist[head * 256 + idx[i]], 1);
}

__global__ void scan_kernel() {
    int head = blockIdx.x;
    int t = threadIdx.x;
    __shared__ int s[256];
    int h = g_hist[head * 256 + t];
    s[t] = h;
    __syncthreads();
    for (int o = 1; o < 256; o <<= 1) {
        int v = (t >= o) ? s[t - o] : 0;
        __syncthreads();
        s[t] += v;
        __syncthreads();
    }
    int excl = s[t] - h;
    g_off[head * 257 + t] = excl;
    g_cursor[head * 256 + t] = excl;
    if (t == 255) g_off[head * 257 + 256] = s[255];
}

__global__ void scatter_kernel(const int* __restrict__ idx, int n, int head, int rowbase) {
    int i = blockIdx.x * blockDim.x + threadIdx.x;
    if (i < n) {
        int b = idx[i];
        int pos = atomicAdd(&g_cursor[head * 256 + b], 1);
        g_order[rowbase + pos] = i;
    }
}

// ---------------- q projection: q = vec @ Aw^T + Ab ----------------
template <int D>
__global__ void __launch_bounds__(256) qproj_kernel(const float* __restrict__ vecs,
                                                    const float* __restrict__ Aw,
                                                    const float* __restrict__ Ab,
                                                    int rowbase) {
    __shared__ float A_s[64 * 33];
    __shared__ float W_s[32 * 33];
    int t = threadIdx.x;
    int row0 = blockIdx.x * 64;
    int col = t & 31;
    int rbase = (t >> 5) * 8;
    float acc[8];
#pragma unroll
    for (int r = 0; r < 8; r++) acc[r] = 0.f;

    for (int k0 = 0; k0 < D; k0 += 32) {
#pragma unroll
        for (int it = 0; it < 8; it++) {
            int m = t + 256 * it;
            int r = m >> 5, kk = m & 31;
            A_s[r * 33 + kk] = vecs[(size_t)(row0 + r) * D + k0 + kk];
        }
#pragma unroll
        for (int it = 0; it < 4; it++) {
            int m = t + 256 * it;
            int c = m >> 5, kk = m & 31;
            W_s[c * 33 + kk] = Aw[(size_t)c * D + k0 + kk];
        }
        __syncthreads();
#pragma unroll
        for (int kk = 0; kk < 32; kk++) {
            float w = W_s[col * 33 + kk];
#pragma unroll
            for (int r = 0; r < 8; r++)
                acc[r] += A_s[(rbase + r) * 33 + kk] * w;
        }
        __syncthreads();
    }
    float bias = Ab[col];
#pragma unroll
    for (int r = 0; r < 8; r++)
        g_q[(size_t)(rowbase + row0 + rbase + r) * LATD + col] = acc[r] + bias;
}

// ---------------- attention: per (head, molecule) bucket, src staged in smem ----------------
__global__ void __launch_bounds__(256) attn_kernel(const float* __restrict__ src) {
    extern __shared__ float smem[];
    float* src_s = smem;              // [400][33] padded
    float* att_s = smem + LSRC * 33;  // [8 warps][400]

    int t = threadIdx.x;
    int b = blockIdx.x;
    int head = blockIdx.y;
    int rowbase = (head == 0) ? 0 : ((head == 1) ? NT : (NT + NA));

    for (int m = t; m < LSRC * LATD; m += 256) {
        int l = m >> 5, k = m & 31;
        src_s[l * 33 + k] = src[(size_t)b * (LSRC * LATD) + m];
    }
    __syncthreads();

    int w = t >> 5, j = t & 31;
    int start = g_off[head * 257 + b];
    int end   = g_off[head * 257 + b + 1];

    for (int ridx = start + w; ridx < end; ridx += 8) {
        int i = g_order[rowbase + ridx];
        const float4* q4 = reinterpret_cast<const float4*>(&g_q[(size_t)(rowbase + i) * LATD]);
        float qr[32];
#pragma unroll
        for (int m = 0; m < 8; m++) {
            float4 v = q4[m];
            qr[4 * m] = v.x; qr[4 * m + 1] = v.y; qr[4 * m + 2] = v.z; qr[4 * m + 3] = v.w;
        }
        float sv[13];
#pragma unroll
        for (int tt = 0; tt < 13; tt++) {
            int l = 32 * tt + j;
            if (l < LSRC) {
                float s = 0.f;
#pragma unroll
                for (int k = 0; k < 32; k++) s += src_s[l * 33 + k] * qr[k];
                sv[tt] = s;
            } else {
                sv[tt] = -INFINITY;
            }
        }
        float mx = -INFINITY;
#pragma unroll
        for (int tt = 0; tt < 13; tt++) mx = fmaxf(mx, sv[tt]);
#pragma unroll
        for (int o = 16; o > 0; o >>= 1) mx = fmaxf(mx, __shfl_xor_sync(0xffffffffu, mx, o));
        float ssum = 0.f;
#pragma unroll
        for (int tt = 0; tt < 13; tt++) {
            float e = (sv[tt] == -INFINITY) ? 0.f : __expf(sv[tt] - mx);
            sv[tt] = e;
            ssum += e;
        }
#pragma unroll
        for (int o = 16; o > 0; o >>= 1) ssum += __shfl_xor_sync(0xffffffffu, ssum, o);
        float inv = 1.f / ssum;
#pragma unroll
        for (int tt = 0; tt < 13; tt++) {
            int l = 32 * tt + j;
            if (l < LSRC) att_s[w * LSRC + l] = sv[tt] * inv;
        }
        __syncwarp();
        float c = 0.f;
#pragma unroll 8
        for (int l = 0; l < LSRC; l++)
            c += att_s[w * LSRC + l] * src_s[l * 33 + j];
        g_cxt[(size_t)(rowbase + i) * LATD + j] = c;
        __syncwarp();
    }
}

// ---------------- fused MLP1 + MLP2 + loss/acc ----------------
template <int D, int C, bool BCE>
__global__ void __launch_bounds__(256) mlp_kernel(const float* __restrict__ vecs,
                                                  const float* __restrict__ w1,
                                                  const float* __restrict__ b1,
                                                  const float* __restrict__ w2,
                                                  const float* __restrict__ b2,
                                                  const int* __restrict__ labels,
                                                  int rowbase, int head) {
    constexpr int K = D + LATD;
    __shared__ float A_s[32 * 33];
    __shared__ float B_s[32 * 257];    // reused as h_s [32][257] in epilogue
    __shared__ float logit_s[32 * C];

    int t = threadIdx.x;
    int row0 = blockIdx.x * 32;
    int col = t & 31;
    int rbase = (t >> 5) * 4;
    float acc[4][8];
#pragma unroll
    for (int rr = 0; rr < 4; rr++)
#pragma unroll
        for (int cc = 0; cc < 8; cc++) acc[rr][cc] = 0.f;

    const float* cxt = g_cxt + (size_t)rowbase * LATD;

    for (int k0 = 0; k0 < K; k0 += 32) {
        if (k0 < D) {
#pragma unroll
            for (int it = 0; it < 4; it++) {
                int m = t + 256 * it;
                int r = m >> 5, kk = m & 31;
                A_s[r * 33 + kk] = vecs[(size_t)(row0 + r) * D + k0 + kk];
            }
        } else {
#pragma unroll
            for (int it = 0; it < 4; it++) {
                int m = t + 256 * it;
                int r = m >> 5, kk = m & 31;
                A_s[r * 33 + kk] = cxt[(size_t)(row0 + r) * LATD + kk];
            }
        }
#pragma unroll
        for (int it = 0; it < 32; it++) {
            int m = t + 256 * it;
            int c = m >> 5, kk = m & 31;
            B_s[kk * 257 + c] = w1[(size_t)c * K + k0 + kk];
        }
        __syncthreads();
#pragma unroll
        for (int kk = 0; kk < 32; kk++) {
            float a[4], bb[8];
#pragma unroll
            for (int rr = 0; rr < 4; rr++) a[rr] = A_s[(rbase + rr) * 33 + kk];
#pragma unroll
            for (int cc = 0; cc < 8; cc++) bb[cc] = B_s[kk * 257 + col + 32 * cc];
#pragma unroll
            for (int rr = 0; rr < 4; rr++)
#pragma unroll
                for (int cc = 0; cc < 8; cc++) acc[rr][cc] += a[rr] * bb[cc];
        }
        __syncthreads();
    }

    // bias + relu -> h staged into B_s
#pragma unroll
    for (int cc = 0; cc < 8; cc++) {
        int c = col + 32 * cc;
        float bias = b1[c];
#pragma unroll
        for (int rr = 0; rr < 4; rr++) {
            float v = acc[rr][cc] + bias;
            B_s[(rbase + rr) * 257 + c] = fmaxf(v, 0.f);
        }
    }
    __syncthreads();

    // logits = h @ w2^T + b2
    for (int p = t; p < 32 * C; p += 256) {
        int r = p / C, cls = p % C;
        float s = b2[cls];
#pragma unroll 8
        for (int k = 0; k < 256; k++) s += B_s[r * 257 + k] * w2[(size_t)cls * 256 + k];
        logit_s[r * C + cls] = s;
    }
    __syncthreads();

    // per-row loss / accuracy, warp 0 only
    if (t < 32) {
        int gi = row0 + t;
        int y = labels[gi];
        float loss;
        int corr;
        if (BCE) {
            float z = logit_s[t];
            float sp = (z > 0.f) ? (z + log1pf(__expf(-z))) : log1pf(__expf(z));
            loss = sp - (float)y * z;
            corr = (((z > 0.f) ? 1 : 0) == y) ? 1 : 0;
        } else {
            float mx = logit_s[t * C];
            int am = 0;
#pragma unroll
            for (int c = 1; c < C; c++) {
                float v = logit_s[t * C + c];
                if (v > mx) { mx = v; am = c; }
            }
            float s = 0.f;
#pragma unroll
            for (int c = 0; c < C; c++) s += __expf(logit_s[t * C + c] - mx);
            loss = logf(s) + mx - logit_s[t * C + y];
            corr = (am == y) ? 1 : 0;
        }
#pragma unroll
        for (int o = 16; o > 0; o >>= 1) {
            loss += __shfl_xor_sync(0xffffffffu, loss, o);
            corr += __shfl_xor_sync(0xffffffffu, corr, o);
        }
        if (t == 0) {
            atomicAdd(&g_loss[head], (double)loss);
            atomicAdd(&g_corr[head], (unsigned int)corr);
        }
    }
}

__global__ void finalize_kernel(float* __restrict__ out) {
    if (threadIdx.x == 0 && blockIdx.x == 0) {
        double L = g_loss[0] + g_loss[1] + g_loss[2];
        out[0] = (float)(L / (double)NBATCH);
        out[1] = (float)g_corr[1] / (float)NA;   // atom_acc
        out[2] = (float)g_corr[0] / (float)NT;   // topo_acc
        out[3] = (float)g_corr[2] / (float)NBD;  // bond_acc
    }
}

// ---------------- launch ----------------
extern "C" void kernel_launch(void* const* d_in, const int* in_sizes, int n_in,
                              void* d_out, int out_size) {
    const float* src        = (const float*)d_in[0];
    const float* topo_vecs  = (const float*)d_in[1];
    const float* atom_vecs  = (const float*)d_in[2];
    const float* bond_vecs  = (const float*)d_in[3];
    const int*   topo_idx   = (const int*)d_in[4];
    const int*   atom_idx   = (const int*)d_in[5];
    const int*   bond_idx   = (const int*)d_in[6];
    const int*   topo_lab   = (const int*)d_in[7];
    const int*   atom_lab   = (const int*)d_in[8];
    const int*   bond_lab   = (const int*)d_in[9];
    const float* A_topo_w   = (const float*)d_in[10];
    const float* A_topo_b   = (const float*)d_in[11];
    const float* A_atom_w   = (const float*)d_in[12];
    const float* A_atom_b   = (const float*)d_in[13];
    const float* A_bond_w   = (const float*)d_in[14];
    const float* A_bond_b   = (const float*)d_in[15];
    const float* topo_w1    = (const float*)d_in[16];
    const float* topo_b1    = (const float*)d_in[17];
    const float* topo_w2    = (const float*)d_in[18];
    const float* topo_b2    = (const float*)d_in[19];
    const float* atom_w1    = (const float*)d_in[20];
    const float* atom_b1    = (const float*)d_in[21];
    const float* atom_w2    = (const float*)d_in[22];
    const float* atom_b2    = (const float*)d_in[23];
    const float* bond_w1    = (const float*)d_in[24];
    const float* bond_b1    = (const float*)d_in[25];
    const float* bond_w2    = (const float*)d_in[26];
    const float* bond_b2    = (const float*)d_in[27];
    float* out = (float*)d_out;

    int attn_smem = (LSRC * 33 + 8 * LSRC) * (int)sizeof(float);
    cudaFuncSetAttribute(attn_kernel, cudaFuncAttributeMaxDynamicSharedMemorySize, attn_smem);

    zero_kernel<<<4, 256>>>();

    hist_kernel<<<(NT + 255) / 256, 256>>>(topo_idx, NT, 0);
    hist_kernel<<<(NA + 255) / 256, 256>>>(atom_idx, NA, 1);
    hist_kernel<<<(NBD + 255) / 256, 256>>>(bond_idx, NBD, 2);
    scan_kernel<<<3, 256>>>();
    scatter_kernel<<<(NT + 255) / 256, 256>>>(topo_idx, NT, 0, 0);
    scatter_kernel<<<(NA + 255) / 256, 256>>>(atom_idx, NA, 1, NT);
    scatter_kernel<<<(NBD + 255) / 256, 256>>>(bond_idx, NBD, 2, NT + NA);

    qproj_kernel<512><<<NT / 64, 256>>>(topo_vecs, A_topo_w, A_topo_b, 0);
    qproj_kernel<512><<<NA / 64, 256>>>(atom_vecs, A_atom_w, A_atom_b, NT);
    qproj_kernel<768><<<NBD / 64, 256>>>(bond_vecs, A_bond_w, A_bond_b, NT + NA);

    attn_kernel<<<dim3(256, 3), 256, attn_smem>>>(src);

    mlp_kernel<512, 1, true><<<NT / 32, 256>>>(topo_vecs, topo_w1, topo_b1, topo_w2, topo_b2, topo_lab, 0, 0);
    mlp_kernel<512, 40, false><<<NA / 32, 256>>>(atom_vecs, atom_w1, atom_b1, atom_w2, atom_b2, atom_lab, NT, 1);
    mlp_kernel<768, 4, false><<<NBD / 32, 256>>>(bond_vecs, bond_w1, bond_b1, bond_w2, bond_b2, bond_lab, NT + NA, 2);

    finalize_kernel<<<1, 1>>>(out);
}

// round 5
// speedup vs baseline: 1.2640x; 1.2640x over previous
#include <cuda_runtime.h>
#include <math.h>

#define NBATCH 256
#define LSRC   400
#define LATD   32
#define NT     38400
#define NA     38400
#define NBD    76800
#define NROWS  (NT + NA + NBD)

#define SRC_P   36    // src_s pitch (floats)
#define SRCT_P  404   // srcT pitch (floats)

// ---------------- scratch (no allocs allowed) ----------------
__device__ float        g_q[(size_t)NROWS * LATD];
__device__ float        g_cxt[(size_t)NROWS * LATD];
__device__ int          g_order[NROWS];
__device__ int          g_hist[3 * 256];
__device__ int          g_cursor[3 * 256];
__device__ int          g_off[3 * 257];
__device__ double       g_loss[3];
__device__ unsigned int g_corr[3];

// ---------------- setup / sort kernels ----------------
__global__ void zero_kernel() {
    int t = blockIdx.x * blockDim.x + threadIdx.x;
    if (t < 3 * 256) { g_hist[t] = 0; g_cursor[t] = 0; }
    if (t < 3) { g_loss[t] = 0.0; g_corr[t] = 0u; }
}

__global__ void hist_kernel(const int* __restrict__ idx, int n, int head) {
    int i = blockIdx.x * blockDim.x + threadIdx.x;
    if (i < n) atomicAdd(&g_hist[head * 256 + idx[i]], 1);
}

__global__ void scan_kernel() {
    int head = blockIdx.x;
    int t = threadIdx.x;
    __shared__ int s[256];
    int h = g_hist[head * 256 + t];
    s[t] = h;
    __syncthreads();
    for (int o = 1; o < 256; o <<= 1) {
        int v = (t >= o) ? s[t - o] : 0;
        __syncthreads();
        s[t] += v;
        __syncthreads();
    }
    int excl = s[t] - h;
    g_off[head * 257 + t] = excl;
    g_cursor[head * 256 + t] = excl;
    if (t == 255) g_off[head * 257 + 256] = s[255];
}

__global__ void scatter_kernel(const int* __restrict__ idx, int n, int head, int rowbase) {
    int i = blockIdx.x * blockDim.x + threadIdx.x;
    if (i < n) {
        int b = idx[i];
        int pos = atomicAdd(&g_cursor[head * 256 + b], 1);
        g_order[rowbase + pos] = i;
    }
}

// ---------------- q projection: q = vec @ Aw^T + Ab (float4 vectorized) ----------------
template <int D>
__global__ void __launch_bounds__(256) qproj_kernel(const float* __restrict__ vecs,
                                                    const float* __restrict__ Aw,
                                                    const float* __restrict__ Ab,
                                                    int rowbase) {
    __shared__ float A_s[64 * 32];
    __shared__ float W_s[32 * 36];
    int t = threadIdx.x;
    int row0 = blockIdx.x * 64;
    int col = t & 31;
    int rbase = (t >> 5) * 8;
    float acc[8];
#pragma unroll
    for (int r = 0; r < 8; r++) acc[r] = 0.f;

    for (int k0 = 0; k0 < D; k0 += 32) {
        // A tile: 64 rows x 32 k -> 512 float4 slots, 2 per thread (coalesced)
#pragma unroll
        for (int it = 0; it < 2; it++) {
            int m = t + 256 * it;
            int r = m >> 3, kq = m & 7;
            *(float4*)&A_s[r * 32 + 4 * kq] =
                *(const float4*)&vecs[(size_t)(row0 + r) * D + k0 + 4 * kq];
        }
        // W tile: 32 cols x 32 k -> 256 float4 slots, 1 per thread
        {
            int c = t >> 3, kq = t & 7;
            *(float4*)&W_s[c * 36 + 4 * kq] =
                *(const float4*)&Aw[(size_t)c * D + k0 + 4 * kq];
        }
        __syncthreads();
#pragma unroll
        for (int kq = 0; kq < 8; kq++) {
            float4 w4 = *(const float4*)&W_s[col * 36 + 4 * kq];
#pragma unroll
            for (int r = 0; r < 8; r++) {
                float4 a4 = *(const float4*)&A_s[(rbase + r) * 32 + 4 * kq];
                acc[r] += a4.x * w4.x + a4.y * w4.y + a4.z * w4.z + a4.w * w4.w;
            }
        }
        __syncthreads();
    }
    float bias = Ab[col];
#pragma unroll
    for (int r = 0; r < 8; r++)
        g_q[(size_t)(rowbase + row0 + rbase + r) * LATD + col] = acc[r] + bias;
}

// ---------------- attention ----------------
// Per (molecule, head) block. src staged twice: src_s[400][36] (k-major, for
// scores w/ float4) and srcT[32][404] (l-major, for float4 weighted sum).
// Each warp processes 4 rows per pass: scores 2 rows at a time (reuses src
// smem reads), softmax, stash att in att_s[32][400], then 4-row float4
// weighted sum.
__global__ void __launch_bounds__(256) attn_kernel(const float* __restrict__ src) {
    extern __shared__ float smem[];
    float* src_s = smem;                          // 400*36
    float* srcT  = smem + LSRC * SRC_P;           // 32*404
    float* att_s = srcT + LATD * SRCT_P;          // 32*400

    int t = threadIdx.x;
    int b = blockIdx.x;
    int head = blockIdx.y;
    int rowbase = (head == 0) ? 0 : ((head == 1) ? NT : (NT + NA));

    for (int m = t; m < LSRC * LATD; m += 256) {
        float v = src[(size_t)b * (LSRC * LATD) + m];
        int l = m >> 5, d = m & 31;
        src_s[l * SRC_P + d] = v;
        srcT[d * SRCT_P + l] = v;
    }
    __syncthreads();

    int w = t >> 5, j = t & 31;
    int start = g_off[head * 257 + b];
    int end   = g_off[head * 257 + b + 1];

    for (int r0 = start + w * 4; r0 < end; r0 += 32) {
        int nr = end - r0; if (nr > 4) nr = 4;

        // ---- scores + softmax, 2 rows at a time ----
#pragma unroll
        for (int pp = 0; pp < 4; pp += 2) {
            int i0 = (pp < nr)     ? g_order[rowbase + r0 + pp]     : g_order[rowbase + r0];
            int i1 = (pp + 1 < nr) ? g_order[rowbase + r0 + pp + 1] : i0;
            float q0r[32], q1r[32];
            const float4* p0 = (const float4*)&g_q[(size_t)(rowbase + i0) * LATD];
            const float4* p1 = (const float4*)&g_q[(size_t)(rowbase + i1) * LATD];
#pragma unroll
            for (int m = 0; m < 8; m++) {
                float4 v0 = p0[m];
                q0r[4*m] = v0.x; q0r[4*m+1] = v0.y; q0r[4*m+2] = v0.z; q0r[4*m+3] = v0.w;
                float4 v1 = p1[m];
                q1r[4*m] = v1.x; q1r[4*m+1] = v1.y; q1r[4*m+2] = v1.z; q1r[4*m+3] = v1.w;
            }
            float sv0[13], sv1[13];
#pragma unroll
            for (int tt = 0; tt < 12; tt++) {
                int l = 32 * tt + j;
                const float* sp = &src_s[l * SRC_P];
                float s0 = 0.f, s1 = 0.f;
#pragma unroll
                for (int kq = 0; kq < 8; kq++) {
                    float4 sr = *(const float4*)&sp[4 * kq];
                    s0 += sr.x*q0r[4*kq] + sr.y*q0r[4*kq+1] + sr.z*q0r[4*kq+2] + sr.w*q0r[4*kq+3];
                    s1 += sr.x*q1r[4*kq] + sr.y*q1r[4*kq+1] + sr.z*q1r[4*kq+2] + sr.w*q1r[4*kq+3];
                }
                sv0[tt] = s0; sv1[tt] = s1;
            }
            {   // tt = 12 (l = 384 + j, valid iff j < 16)
                int l = 384 + j;
                if (l < LSRC) {
                    const float* sp = &src_s[l * SRC_P];
                    float s0 = 0.f, s1 = 0.f;
#pragma unroll
                    for (int kq = 0; kq < 8; kq++) {
                        float4 sr = *(const float4*)&sp[4 * kq];
                        s0 += sr.x*q0r[4*kq] + sr.y*q0r[4*kq+1] + sr.z*q0r[4*kq+2] + sr.w*q0r[4*kq+3];
                        s1 += sr.x*q1r[4*kq] + sr.y*q1r[4*kq+1] + sr.z*q1r[4*kq+2] + sr.w*q1r[4*kq+3];
                    }
                    sv0[12] = s0; sv1[12] = s1;
                } else { sv0[12] = -INFINITY; sv1[12] = -INFINITY; }
            }
            // softmax (both rows)
            float mx0 = -INFINITY, mx1 = -INFINITY;
#pragma unroll
            for (int tt = 0; tt < 13; tt++) { mx0 = fmaxf(mx0, sv0[tt]); mx1 = fmaxf(mx1, sv1[tt]); }
#pragma unroll
            for (int o = 16; o > 0; o >>= 1) {
                mx0 = fmaxf(mx0, __shfl_xor_sync(0xffffffffu, mx0, o));
                mx1 = fmaxf(mx1, __shfl_xor_sync(0xffffffffu, mx1, o));
            }
            float ss0 = 0.f, ss1 = 0.f;
#pragma unroll
            for (int tt = 0; tt < 13; tt++) {
                float e0 = (sv0[tt] == -INFINITY) ? 0.f : __expf(sv0[tt] - mx0);
                float e1 = (sv1[tt] == -INFINITY) ? 0.f : __expf(sv1[tt] - mx1);
                sv0[tt] = e0; sv1[tt] = e1; ss0 += e0; ss1 += e1;
            }
#pragma unroll
            for (int o = 16; o > 0; o >>= 1) {
                ss0 += __shfl_xor_sync(0xffffffffu, ss0, o);
                ss1 += __shfl_xor_sync(0xffffffffu, ss1, o);
            }
            float inv0 = 1.f / ss0, inv1 = 1.f / ss1;
            float* a0 = &att_s[(w * 4 + pp) * LSRC];
            float* a1 = &att_s[(w * 4 + pp + 1) * LSRC];
#pragma unroll
            for (int tt = 0; tt < 13; tt++) {
                int l = 32 * tt + j;
                if (l < LSRC) { a0[l] = sv0[tt] * inv0; a1[l] = sv1[tt] * inv1; }
            }
        }
        __syncwarp();

        // ---- weighted sum: 4 rows, float4 over l ----
        float c0 = 0.f, c1 = 0.f, c2 = 0.f, c3 = 0.f;
        const float4* vt = (const float4*)&srcT[j * SRCT_P];
        const float4* a0 = (const float4*)&att_s[(w * 4 + 0) * LSRC];
        const float4* a1 = (const float4*)&att_s[(w * 4 + 1) * LSRC];
        const float4* a2 = (const float4*)&att_s[(w * 4 + 2) * LSRC];
        const float4* a3 = (const float4*)&att_s[(w * 4 + 3) * LSRC];
#pragma unroll 4
        for (int lq = 0; lq < LSRC / 4; lq++) {
            float4 v  = vt[lq];
            float4 x0 = a0[lq]; c0 += x0.x*v.x + x0.y*v.y + x0.z*v.z + x0.w*v.w;
            float4 x1 = a1[lq]; c1 += x1.x*v.x + x1.y*v.y + x1.z*v.z + x1.w*v.w;
            float4 x2 = a2[lq]; c2 += x2.x*v.x + x2.y*v.y + x2.z*v.z + x2.w*v.w;
            float4 x3 = a3[lq]; c3 += x3.x*v.x + x3.y*v.y + x3.z*v.z + x3.w*v.w;
        }
        float cv[4] = {c0, c1, c2, c3};
        for (int rr = 0; rr < nr; rr++) {
            int i = g_order[rowbase + r0 + rr];
            g_cxt[(size_t)(rowbase + i) * LATD + j] = cv[rr];
        }
        __syncwarp();
    }
}

// ---------------- fused MLP1 + MLP2 + loss/acc (64x256 tile, 8x8/thread) ----------------
template <int D, int C, bool BCE>
__global__ void __launch_bounds__(256) mlp_kernel(const float* __restrict__ vecs,
                                                  const float* __restrict__ w1,
                                                  const float* __restrict__ b1,
                                                  const float* __restrict__ w2,
                                                  const float* __restrict__ b2,
                                                  const int* __restrict__ labels,
                                                  int rowbase, int head) {
    constexpr int K = D + LATD;
    constexpr int HP = 264;  // h_s pitch
    extern __shared__ float sm[];
    float* A_s     = sm;                    // 64*36
    float* B_s     = A_s + 64 * 36;         // 256*36  (w1 tile, [c][k])
    float* h_s     = B_s + 256 * 36;        // 64*HP
    float* logit_s = h_s + 64 * HP;         // 64*C
    float* red     = logit_s + 64 * C;      // 128

    int t = threadIdx.x;
    int row0 = blockIdx.x * 64;
    int w = t >> 5, j = t & 31;
    float acc[8][8];
#pragma unroll
    for (int rr = 0; rr < 8; rr++)
#pragma unroll
        for (int cc = 0; cc < 8; cc++) acc[rr][cc] = 0.f;

    const float* cxt = g_cxt + (size_t)rowbase * LATD;

    for (int k0 = 0; k0 < K; k0 += 32) {
        // A tile: 64 rows x 32 k (from vecs, last chunk from cxt)
        if (k0 < D) {
#pragma unroll
            for (int it = 0; it < 2; it++) {
                int m = t + 256 * it;
                int r = m >> 3, kq = m & 7;
                *(float4*)&A_s[r * 36 + 4 * kq] =
                    *(const float4*)&vecs[(size_t)(row0 + r) * D + k0 + 4 * kq];
            }
        } else {
#pragma unroll
            for (int it = 0; it < 2; it++) {
                int m = t + 256 * it;
                int r = m >> 3, kq = m & 7;
                *(float4*)&A_s[r * 36 + 4 * kq] =
                    *(const float4*)&cxt[(size_t)(row0 + r) * LATD + 4 * kq];
            }
        }
        // B tile: 256 cols x 32 k, native w1 layout [c][k]
#pragma unroll
        for (int it = 0; it < 8; it++) {
            int m = t + 256 * it;
            int c = m >> 3, kq = m & 7;
            *(float4*)&B_s[c * 36 + 4 * kq] =
                *(const float4*)&w1[(size_t)c * K + k0 + 4 * kq];
        }
        __syncthreads();
#pragma unroll
        for (int kq = 0; kq < 8; kq++) {
            float4 b4[8];
#pragma unroll
            for (int cc = 0; cc < 8; cc++)
                b4[cc] = *(const float4*)&B_s[(j + 32 * cc) * 36 + 4 * kq];
#pragma unroll
            for (int rr = 0; rr < 8; rr++) {
                float4 a4 = *(const float4*)&A_s[(w * 8 + rr) * 36 + 4 * kq];
#pragma unroll
                for (int cc = 0; cc < 8; cc++)
                    acc[rr][cc] += a4.x * b4[cc].x + a4.y * b4[cc].y
                                 + a4.z * b4[cc].z + a4.w * b4[cc].w;
            }
        }
        __syncthreads();
    }

    // bias + relu -> h_s
#pragma unroll
    for (int cc = 0; cc < 8; cc++) {
        int c = j + 32 * cc;
        float bias = b1[c];
#pragma unroll
        for (int rr = 0; rr < 8; rr++)
            h_s[(w * 8 + rr) * HP + c] = fmaxf(acc[rr][cc] + bias, 0.f);
    }
    __syncthreads();

    // logits = h @ w2^T + b2 (float4 dots; w2 stays L1-resident across blocks)
    for (int p = t; p < 64 * C; p += 256) {
        int r = p / C, cls = p - r * C;
        const float4* hp = (const float4*)&h_s[r * HP];
        const float4* wp = (const float4*)&w2[(size_t)cls * 256];
        float s = 0.f;
#pragma unroll 8
        for (int kq = 0; kq < 64; kq++) {
            float4 h4 = hp[kq]; float4 w4 = wp[kq];
            s += h4.x*w4.x + h4.y*w4.y + h4.z*w4.z + h4.w*w4.w;
        }
        logit_s[p] = s + b2[cls];
    }
    __syncthreads();

    // per-row loss / accuracy
    if (t < 64) {
        int gi = row0 + t;
        int y = labels[gi];
        float loss;
        int corr;
        if (BCE) {
            float z = logit_s[t];
            float sp = (z > 0.f) ? (z + log1pf(__expf(-z))) : log1pf(__expf(z));
            loss = sp - (float)y * z;
            corr = (((z > 0.f) ? 1 : 0) == y) ? 1 : 0;
        } else {
            float mx = logit_s[t * C];
            int am = 0;
#pragma unroll
            for (int c = 1; c < C; c++) {
                float v = logit_s[t * C + c];
                if (v > mx) { mx = v; am = c; }
            }
            float s = 0.f;
#pragma unroll
            for (int c = 0; c < C; c++) s += __expf(logit_s[t * C + c] - mx);
            loss = logf(s) + mx - logit_s[t * C + y];
            corr = (am == y) ? 1 : 0;
        }
        red[t] = loss;
        ((int*)red)[64 + t] = corr;
    }
    __syncthreads();
    if (t < 32) {
        float L = red[t] + red[t + 32];
        int Ck = ((int*)red)[64 + t] + ((int*)red)[64 + t + 32];
#pragma unroll
        for (int o = 16; o > 0; o >>= 1) {
            L += __shfl_xor_sync(0xffffffffu, L, o);
            Ck += __shfl_xor_sync(0xffffffffu, Ck, o);
        }
        if (t == 0) {
            atomicAdd(&g_loss[head], (double)L);
            atomicAdd(&g_corr[head], (unsigned int)Ck);
        }
    }
}

__global__ void finalize_kernel(float* __restrict__ out) {
    if (threadIdx.x == 0 && blockIdx.x == 0) {
        double L = g_loss[0] + g_loss[1] + g_loss[2];
        out[0] = (float)(L / (double)NBATCH);
        out[1] = (float)g_corr[1] / (float)NA;   // atom_acc
        out[2] = (float)g_corr[0] / (float)NT;   // topo_acc
        out[3] = (float)g_corr[2] / (float)NBD;  // bond_acc
    }
}

// ---------------- launch ----------------
extern "C" void kernel_launch(void* const* d_in, const int* in_sizes, int n_in,
                              void* d_out, int out_size) {
    const float* src        = (const float*)d_in[0];
    const float* topo_vecs  = (const float*)d_in[1];
    const float* atom_vecs  = (const float*)d_in[2];
    const float* bond_vecs  = (const float*)d_in[3];
    const int*   topo_idx   = (const int*)d_in[4];
    const int*   atom_idx   = (const int*)d_in[5];
    const int*   bond_idx   = (const int*)d_in[6];
    const int*   topo_lab   = (const int*)d_in[7];
    const int*   atom_lab   = (const int*)d_in[8];
    const int*   bond_lab   = (const int*)d_in[9];
    const float* A_topo_w   = (const float*)d_in[10];
    const float* A_topo_b   = (const float*)d_in[11];
    const float* A_atom_w   = (const float*)d_in[12];
    const float* A_atom_b   = (const float*)d_in[13];
    const float* A_bond_w   = (const float*)d_in[14];
    const float* A_bond_b   = (const float*)d_in[15];
    const float* topo_w1    = (const float*)d_in[16];
    const float* topo_b1    = (const float*)d_in[17];
    const float* topo_w2    = (const float*)d_in[18];
    const float* topo_b2    = (const float*)d_in[19];
    const float* atom_w1    = (const float*)d_in[20];
    const float* atom_b1    = (const float*)d_in[21];
    const float* atom_w2    = (const float*)d_in[22];
    const float* atom_b2    = (const float*)d_in[23];
    const float* bond_w1    = (const float*)d_in[24];
    const float* bond_b1    = (const float*)d_in[25];
    const float* bond_w2    = (const float*)d_in[26];
    const float* bond_b2    = (const float*)d_in[27];
    float* out = (float*)d_out;

    int attn_smem = (LSRC * SRC_P + LATD * SRCT_P + 32 * LSRC) * (int)sizeof(float);
    static bool attr_done = false;
    if (!attr_done) {
        cudaFuncSetAttribute(attn_kernel, cudaFuncAttributeMaxDynamicSharedMemorySize, attn_smem);
        cudaFuncSetAttribute(mlp_kernel<512, 1, true>,  cudaFuncAttributeMaxDynamicSharedMemorySize,
                             (64*36 + 256*36 + 64*264 + 64*1 + 128) * (int)sizeof(float));
        cudaFuncSetAttribute(mlp_kernel<512, 40, false>, cudaFuncAttributeMaxDynamicSharedMemorySize,
                             (64*36 + 256*36 + 64*264 + 64*40 + 128) * (int)sizeof(float));
        cudaFuncSetAttribute(mlp_kernel<768, 4, false>,  cudaFuncAttributeMaxDynamicSharedMemorySize,
                             (64*36 + 256*36 + 64*264 + 64*4 + 128) * (int)sizeof(float));
        attr_done = true;
    }

    zero_kernel<<<4, 256>>>();

    hist_kernel<<<(NT + 255) / 256, 256>>>(topo_idx, NT, 0);
    hist_kernel<<<(NA + 255) / 256, 256>>>(atom_idx, NA, 1);
    hist_kernel<<<(NBD + 255) / 256, 256>>>(bond_idx, NBD, 2);
    scan_kernel<<<3, 256>>>();
    scatter_kernel<<<(NT + 255) / 256, 256>>>(topo_idx, NT, 0, 0);
    scatter_kernel<<<(NA + 255) / 256, 256>>>(atom_idx, NA, 1, NT);
    scatter_kernel<<<(NBD + 255) / 256, 256>>>(bond_idx, NBD, 2, NT + NA);

    qproj_kernel<512><<<NT / 64, 256>>>(topo_vecs, A_topo_w, A_topo_b, 0);
    qproj_kernel<512><<<NA / 64, 256>>>(atom_vecs, A_atom_w, A_atom_b, NT);
    qproj_kernel<768><<<NBD / 64, 256>>>(bond_vecs, A_bond_w, A_bond_b, NT + NA);

    attn_kernel<<<dim3(256, 3), 256, attn_smem>>>(src);

    mlp_kernel<512, 1, true><<<NT / 64, 256,
        (64*36 + 256*36 + 64*264 + 64*1 + 128) * (int)sizeof(float)>>>(
        topo_vecs, topo_w1, topo_b1, topo_w2, topo_b2, topo_lab, 0, 0);
    mlp_kernel<512, 40, false><<<NA / 64, 256,
        (64*36 + 256*36 + 64*264 + 64*40 + 128) * (int)sizeof(float)>>>(
        atom_vecs, atom_w1, atom_b1, atom_w2, atom_b2, atom_lab, NT, 1);
    mlp_kernel<768, 4, false><<<NBD / 64, 256,
        (64*36 + 256*36 + 64*264 + 64*4 + 128) * (int)sizeof(float)>>>(
        bond_vecs, bond_w1, bond_b1, bond_w2, bond_b2, bond_lab, NT + NA, 2);

    finalize_kernel<<<1, 1>>>(out);
}

// round 8
// speedup vs baseline: 1.4670x; 1.1606x over previous
#include <cuda_runtime.h>
#include <math.h>

#define NBATCH 256
#define LSRC   400
#define LATD   32
#define NT     38400
#define NA     38400
#define NBD    76800
#define NROWS  (NT + NA + NBD)

#define SRC_P   36    // src_s pitch (floats)
#define SRCT_P  404   // srcT pitch (floats)

typedef unsigned long long u64;

// packed fp32x2 FMA: acc(2 lanes) += a(2 lanes) * b(2 lanes)
__device__ __forceinline__ void ffma2(u64& acc, u64 a, u64 b) {
    asm("fma.rn.f32x2 %0, %1, %2, %0;" : "+l"(acc) : "l"(a), "l"(b));
}
__device__ __forceinline__ float hadd2(u64 p) {
    float2 f = *reinterpret_cast<float2*>(&p);
    return f.x + f.y;
}

// ---------------- scratch (no allocs allowed) ----------------
__device__ __align__(16) float g_q[(size_t)NROWS * LATD];
__device__ __align__(16) float g_cxt[(size_t)NROWS * LATD];
__device__ int          g_order[NROWS];
__device__ int          g_hist[3 * 256];
__device__ int          g_cursor[3 * 256];
__device__ int          g_off[3 * 257];
__device__ double       g_loss[3];
__device__ unsigned int g_corr[3];

// ---------------- setup / sort kernels ----------------
__global__ void zero_kernel() {
    int t = blockIdx.x * blockDim.x + threadIdx.x;
    if (t < 3 * 256) { g_hist[t] = 0; g_cursor[t] = 0; }
    if (t < 3) { g_loss[t] = 0.0; g_corr[t] = 0u; }
}

__global__ void hist3_kernel(const int* __restrict__ ti, const int* __restrict__ ai,
                             const int* __restrict__ bi) {
    int i = blockIdx.x * blockDim.x + threadIdx.x;
    if (i < NT)  atomicAdd(&g_hist[0 * 256 + ti[i]], 1);
    if (i < NA)  atomicAdd(&g_hist[1 * 256 + ai[i]], 1);
    if (i < NBD) atomicAdd(&g_hist[2 * 256 + bi[i]], 1);
}

__global__ void scan_kernel() {
    int head = blockIdx.x;
    int t = threadIdx.x;
    __shared__ int s[256];
    int h = g_hist[head * 256 + t];
    s[t] = h;
    __syncthreads();
    for (int o = 1; o < 256; o <<= 1) {
        int v = (t >= o) ? s[t - o] : 0;
        __syncthreads();
        s[t] += v;
        __syncthreads();
    }
    int excl = s[t] - h;
    g_off[head * 257 + t] = excl;
    g_cursor[head * 256 + t] = excl;
    if (t == 255) g_off[head * 257 + 256] = s[255];
}

__global__ void scatter3_kernel(const int* __restrict__ ti, const int* __restrict__ ai,
                                const int* __restrict__ bi) {
    int i = blockIdx.x * blockDim.x + threadIdx.x;
    if (i < NT) {
        int b = ti[i];
        int pos = atomicAdd(&g_cursor[0 * 256 + b], 1);
        g_order[pos] = i;
    }
    if (i < NA) {
        int b = ai[i];
        int pos = atomicAdd(&g_cursor[1 * 256 + b], 1);
        g_order[NT + pos] = i;
    }
    if (i < NBD) {
        int b = bi[i];
        int pos = atomicAdd(&g_cursor[2 * 256 + b], 1);
        g_order[NT + NA + pos] = i;
    }
}

// ---------------- q projection: q = vec @ Aw^T + Ab (FFMA2 over k-pairs) ----------------
template <int D>
__global__ void __launch_bounds__(256) qproj_kernel(const float* __restrict__ vecs,
                                                    const float* __restrict__ Aw,
                                                    const float* __restrict__ Ab,
                                                    int rowbase) {
    __shared__ __align__(16) float A_s[64 * 32];
    __shared__ __align__(16) float W_s[32 * 36];
    int t = threadIdx.x;
    int row0 = blockIdx.x * 64;
    int col = t & 31;
    int rbase = (t >> 5) * 8;
    u64 acc[8];
#pragma unroll
    for (int r = 0; r < 8; r++) acc[r] = 0ull;

    for (int k0 = 0; k0 < D; k0 += 32) {
#pragma unroll
        for (int it = 0; it < 2; it++) {
            int m = t + 256 * it;
            int r = m >> 3, kq = m & 7;
            *(float4*)&A_s[r * 32 + 4 * kq] =
                *(const float4*)&vecs[(size_t)(row0 + r) * D + k0 + 4 * kq];
        }
        {
            int c = t >> 3, kq = t & 7;
            *(float4*)&W_s[c * 36 + 4 * kq] =
                *(const float4*)&Aw[(size_t)c * D + k0 + 4 * kq];
        }
        __syncthreads();
#pragma unroll
        for (int kq = 0; kq < 8; kq++) {
            ulonglong2 w4 = *(const ulonglong2*)&W_s[col * 36 + 4 * kq];
#pragma unroll
            for (int r = 0; r < 8; r++) {
                ulonglong2 a4 = *(const ulonglong2*)&A_s[(rbase + r) * 32 + 4 * kq];
                ffma2(acc[r], a4.x, w4.x);
                ffma2(acc[r], a4.y, w4.y);
            }
        }
        __syncthreads();
    }
    float bias = Ab[col];
#pragma unroll
    for (int r = 0; r < 8; r++)
        g_q[(size_t)(rowbase + row0 + rbase + r) * LATD + col] = hadd2(acc[r]) + bias;
}

// ---------------- attention (FFMA2 in scores + weighted sum) ----------------
__global__ void __launch_bounds__(256) attn_kernel(const float* __restrict__ src) {
    extern __shared__ __align__(16) float smem[];
    float* src_s = smem;                          // 400*36
    float* srcT  = smem + LSRC * SRC_P;           // 32*404
    float* att_s = srcT + LATD * SRCT_P;          // 32*400

    int t = threadIdx.x;
    int b = blockIdx.x;
    int head = blockIdx.y;
    int rowbase = (head == 0) ? 0 : ((head == 1) ? NT : (NT + NA));

    for (int m = t; m < LSRC * LATD; m += 256) {
        float v = src[(size_t)b * (LSRC * LATD) + m];
        int l = m >> 5, d = m & 31;
        src_s[l * SRC_P + d] = v;
        srcT[d * SRCT_P + l] = v;
    }
    __syncthreads();

    int w = t >> 5, j = t & 31;
    int start = g_off[head * 257 + b];
    int end   = g_off[head * 257 + b + 1];

    for (int r0 = start + w * 4; r0 < end; r0 += 32) {
        int nr = end - r0; if (nr > 4) nr = 4;

        // ---- scores + softmax, 2 rows at a time ----
#pragma unroll
        for (int pp = 0; pp < 4; pp += 2) {
            int i0 = (pp < nr)     ? g_order[rowbase + r0 + pp]     : g_order[rowbase + r0];
            int i1 = (pp + 1 < nr) ? g_order[rowbase + r0 + pp + 1] : i0;
            u64 q0p[16], q1p[16];
            const ulonglong2* p0 = (const ulonglong2*)&g_q[(size_t)(rowbase + i0) * LATD];
            const ulonglong2* p1 = (const ulonglong2*)&g_q[(size_t)(rowbase + i1) * LATD];
#pragma unroll
            for (int m = 0; m < 8; m++) {
                ulonglong2 v0 = p0[m]; q0p[2 * m] = v0.x; q0p[2 * m + 1] = v0.y;
                ulonglong2 v1 = p1[m]; q1p[2 * m] = v1.x; q1p[2 * m + 1] = v1.y;
            }
            float sv0[13], sv1[13];
#pragma unroll
            for (int tt = 0; tt < 12; tt++) {
                int l = 32 * tt + j;
                const ulonglong2* sp = (const ulonglong2*)&src_s[l * SRC_P];
                u64 s0p = 0ull, s1p = 0ull;
#pragma unroll
                for (int kq = 0; kq < 8; kq++) {
                    ulonglong2 sr = sp[kq];
                    ffma2(s0p, sr.x, q0p[2 * kq]); ffma2(s0p, sr.y, q0p[2 * kq + 1]);
                    ffma2(s1p, sr.x, q1p[2 * kq]); ffma2(s1p, sr.y, q1p[2 * kq + 1]);
                }
                sv0[tt] = hadd2(s0p); sv1[tt] = hadd2(s1p);
            }
            {   // tt = 12 (l = 384 + j, valid iff j < 16)
                int l = 384 + j;
                if (l < LSRC) {
                    const ulonglong2* sp = (const ulonglong2*)&src_s[l * SRC_P];
                    u64 s0p = 0ull, s1p = 0ull;
#pragma unroll
                    for (int kq = 0; kq < 8; kq++) {
                        ulonglong2 sr = sp[kq];
                        ffma2(s0p, sr.x, q0p[2 * kq]); ffma2(s0p, sr.y, q0p[2 * kq + 1]);
                        ffma2(s1p, sr.x, q1p[2 * kq]); ffma2(s1p, sr.y, q1p[2 * kq + 1]);
                    }
                    sv0[12] = hadd2(s0p); sv1[12] = hadd2(s1p);
                } else { sv0[12] = -INFINITY; sv1[12] = -INFINITY; }
            }
            float mx0 = -INFINITY, mx1 = -INFINITY;
#pragma unroll
            for (int tt = 0; tt < 13; tt++) { mx0 = fmaxf(mx0, sv0[tt]); mx1 = fmaxf(mx1, sv1[tt]); }
#pragma unroll
            for (int o = 16; o > 0; o >>= 1) {
                mx0 = fmaxf(mx0, __shfl_xor_sync(0xffffffffu, mx0, o));
                mx1 = fmaxf(mx1, __shfl_xor_sync(0xffffffffu, mx1, o));
            }
            float ss0 = 0.f, ss1 = 0.f;
#pragma unroll
            for (int tt = 0; tt < 13; tt++) {
                float e0 = (sv0[tt] == -INFINITY) ? 0.f : __expf(sv0[tt] - mx0);
                float e1 = (sv1[tt] == -INFINITY) ? 0.f : __expf(sv1[tt] - mx1);
                sv0[tt] = e0; sv1[tt] = e1; ss0 += e0; ss1 += e1;
            }
#pragma unroll
            for (int o = 16; o > 0; o >>= 1) {
                ss0 += __shfl_xor_sync(0xffffffffu, ss0, o);
                ss1 += __shfl_xor_sync(0xffffffffu, ss1, o);
            }
            float inv0 = 1.f / ss0, inv1 = 1.f / ss1;
            float* a0 = &att_s[(w * 4 + pp) * LSRC];
            float* a1 = &att_s[(w * 4 + pp + 1) * LSRC];
#pragma unroll
            for (int tt = 0; tt < 13; tt++) {
                int l = 32 * tt + j;
                if (l < LSRC) { a0[l] = sv0[tt] * inv0; a1[l] = sv1[tt] * inv1; }
            }
        }
        __syncwarp();

        // ---- weighted sum: 4 rows, FFMA2 over l-pairs ----
        u64 c0p = 0ull, c1p = 0ull, c2p = 0ull, c3p = 0ull;
        const ulonglong2* vt = (const ulonglong2*)&srcT[j * SRCT_P];
        const ulonglong2* a0 = (const ulonglong2*)&att_s[(w * 4 + 0) * LSRC];
        const ulonglong2* a1 = (const ulonglong2*)&att_s[(w * 4 + 1) * LSRC];
        const ulonglong2* a2 = (const ulonglong2*)&att_s[(w * 4 + 2) * LSRC];
        const ulonglong2* a3 = (const ulonglong2*)&att_s[(w * 4 + 3) * LSRC];
#pragma unroll 4
        for (int lq = 0; lq < LSRC / 4; lq++) {
            ulonglong2 v  = vt[lq];
            ulonglong2 x0 = a0[lq]; ffma2(c0p, x0.x, v.x); ffma2(c0p, x0.y, v.y);
            ulonglong2 x1 = a1[lq]; ffma2(c1p, x1.x, v.x); ffma2(c1p, x1.y, v.y);
            ulonglong2 x2 = a2[lq]; ffma2(c2p, x2.x, v.x); ffma2(c2p, x2.y, v.y);
            ulonglong2 x3 = a3[lq]; ffma2(c3p, x3.x, v.x); ffma2(c3p, x3.y, v.y);
        }
        float cv[4] = {hadd2(c0p), hadd2(c1p), hadd2(c2p), hadd2(c3p)};
        for (int rr = 0; rr < nr; rr++) {
            int i = g_order[rowbase + r0 + rr];
            g_cxt[(size_t)(rowbase + i) * LATD + j] = cv[rr];
        }
        __syncwarp();
    }
}

// ---------------- fused MLP1 + MLP2 + loss/acc (64x256 tile, FFMA2 8x8) ----------------
template <int D, int C, bool BCE>
__global__ void __launch_bounds__(256) mlp_kernel(const float* __restrict__ vecs,
                                                  const float* __restrict__ w1,
                                                  const float* __restrict__ b1,
                                                  const float* __restrict__ w2,
                                                  const float* __restrict__ b2,
                                                  const int* __restrict__ labels,
                                                  int rowbase, int head) {
    constexpr int K = D + LATD;
    constexpr int HP = 264;  // h_s pitch
    extern __shared__ __align__(16) float sm[];
    float* A_s     = sm;                    // 64*36
    float* B_s     = A_s + 64 * 36;         // 256*36  (w1 tile, [c][k])
    float* h_s     = B_s + 256 * 36;        // 64*HP
    float* logit_s = h_s + 64 * HP;         // 64*C
    float* red     = logit_s + 64 * C;      // 128

    int t = threadIdx.x;
    int row0 = blockIdx.x * 64;
    int w = t >> 5, j = t & 31;
    u64 acc[8][8];
#pragma unroll
    for (int rr = 0; rr < 8; rr++)
#pragma unroll
        for (int cc = 0; cc < 8; cc++) acc[rr][cc] = 0ull;

    const float* cxt = g_cxt + (size_t)rowbase * LATD;

    for (int k0 = 0; k0 < K; k0 += 32) {
        if (k0 < D) {
#pragma unroll
            for (int it = 0; it < 2; it++) {
                int m = t + 256 * it;
                int r = m >> 3, kq = m & 7;
                *(float4*)&A_s[r * 36 + 4 * kq] =
                    *(const float4*)&vecs[(size_t)(row0 + r) * D + k0 + 4 * kq];
            }
        } else {
#pragma unroll
            for (int it = 0; it < 2; it++) {
                int m = t + 256 * it;
                int r = m >> 3, kq = m & 7;
                *(float4*)&A_s[r * 36 + 4 * kq] =
                    *(const float4*)&cxt[(size_t)(row0 + r) * LATD + 4 * kq];
            }
        }
#pragma unroll
        for (int it = 0; it < 8; it++) {
            int m = t + 256 * it;
            int c = m >> 3, kq = m & 7;
            *(float4*)&B_s[c * 36 + 4 * kq] =
                *(const float4*)&w1[(size_t)c * K + k0 + 4 * kq];
        }
        __syncthreads();
#pragma unroll
        for (int kq = 0; kq < 8; kq++) {
            ulonglong2 b4[8];
#pragma unroll
            for (int cc = 0; cc < 8; cc++)
                b4[cc] = *(const ulonglong2*)&B_s[(j + 32 * cc) * 36 + 4 * kq];
#pragma unroll
            for (int rr = 0; rr < 8; rr++) {
                ulonglong2 a4 = *(const ulonglong2*)&A_s[(w * 8 + rr) * 36 + 4 * kq];
#pragma unroll
                for (int cc = 0; cc < 8; cc++) {
                    ffma2(acc[rr][cc], a4.x, b4[cc].x);
                    ffma2(acc[rr][cc], a4.y, b4[cc].y);
                }
            }
        }
        __syncthreads();
    }

    // bias + relu -> h_s
#pragma unroll
    for (int cc = 0; cc < 8; cc++) {
        int c = j + 32 * cc;
        float bias = b1[c];
#pragma unroll
        for (int rr = 0; rr < 8; rr++)
            h_s[(w * 8 + rr) * HP + c] = fmaxf(hadd2(acc[rr][cc]) + bias, 0.f);
    }
    __syncthreads();

    // logits = h @ w2^T + b2 (FFMA2 dots; w2 stays L1/L2-resident across blocks)
    for (int p = t; p < 64 * C; p += 256) {
        int r = p / C, cls = p - r * C;
        const ulonglong2* hp = (const ulonglong2*)&h_s[r * HP];
        const ulonglong2* wp = (const ulonglong2*)&w2[(size_t)cls * 256];
        u64 sp2 = 0ull;
#pragma unroll 8
        for (int kq = 0; kq < 64; kq++) {
            ulonglong2 h4 = hp[kq]; ulonglong2 w4 = wp[kq];
            ffma2(sp2, h4.x, w4.x); ffma2(sp2, h4.y, w4.y);
        }
        logit_s[p] = hadd2(sp2) + b2[cls];
    }
    __syncthreads();

    // per-row loss / accuracy
    if (t < 64) {
        int gi = row0 + t;
        int y = labels[gi];
        float loss;
        int corr;
        if (BCE) {
            float z = logit_s[t];
            float sp = (z > 0.f) ? (z + log1pf(__expf(-z))) : log1pf(__expf(z));
            loss = sp - (float)y * z;
            corr = (((z > 0.f) ? 1 : 0) == y) ? 1 : 0;
        } else {
            float mx = logit_s[t * C];
            int am = 0;
#pragma unroll
            for (int c = 1; c < C; c++) {
                float v = logit_s[t * C + c];
                if (v > mx) { mx = v; am = c; }
            }
            float s = 0.f;
#pragma unroll
            for (int c = 0; c < C; c++) s += __expf(logit_s[t * C + c] - mx);
            loss = logf(s) + mx - logit_s[t * C + y];
            corr = (am == y) ? 1 : 0;
        }
        red[t] = loss;
        ((int*)red)[64 + t] = corr;
    }
    __syncthreads();
    if (t < 32) {
        float L = red[t] + red[t + 32];
        int Ck = ((int*)red)[64 + t] + ((int*)red)[64 + t + 32];
#pragma unroll
        for (int o = 16; o > 0; o >>= 1) {
            L += __shfl_xor_sync(0xffffffffu, L, o);
            Ck += __shfl_xor_sync(0xffffffffu, Ck, o);
        }
        if (t == 0) {
            atomicAdd(&g_loss[head], (double)L);
            atomicAdd(&g_corr[head], (unsigned int)Ck);
        }
    }
}

__global__ void finalize_kernel(float* __restrict__ out) {
    if (threadIdx.x == 0 && blockIdx.x == 0) {
        double L = g_loss[0] + g_loss[1] + g_loss[2];
        out[0] = (float)(L / (double)NBATCH);
        out[1] = (float)g_corr[1] / (float)NA;   // atom_acc
        out[2] = (float)g_corr[0] / (float)NT;   // topo_acc
        out[3] = (float)g_corr[2] / (float)NBD;  // bond_acc
    }
}

// ---------------- launch ----------------
extern "C" void kernel_launch(void* const* d_in, const int* in_sizes, int n_in,
                              void* d_out, int out_size) {
    const float* src        = (const float*)d_in[0];
    const float* topo_vecs  = (const float*)d_in[1];
    const float* atom_vecs  = (const float*)d_in[2];
    const float* bond_vecs  = (const float*)d_in[3];
    const int*   topo_idx   = (const int*)d_in[4];
    const int*   atom_idx   = (const int*)d_in[5];
    const int*   bond_idx   = (const int*)d_in[6];
    const int*   topo_lab   = (const int*)d_in[7];
    const int*   atom_lab   = (const int*)d_in[8];
    const int*   bond_lab   = (const int*)d_in[9];
    const float* A_topo_w   = (const float*)d_in[10];
    const float* A_topo_b   = (const float*)d_in[11];
    const float* A_atom_w   = (const float*)d_in[12];
    const float* A_atom_b   = (const float*)d_in[13];
    const float* A_bond_w   = (const float*)d_in[14];
    const float* A_bond_b   = (const float*)d_in[15];
    const float* topo_w1    = (const float*)d_in[16];
    const float* topo_b1    = (const float*)d_in[17];
    const float* topo_w2    = (const float*)d_in[18];
    const float* topo_b2    = (const float*)d_in[19];
    const float* atom_w1    = (const float*)d_in[20];
    const float* atom_b1    = (const float*)d_in[21];
    const float* atom_w2    = (const float*)d_in[22];
    const float* atom_b2    = (const float*)d_in[23];
    const float* bond_w1    = (const float*)d_in[24];
    const float* bond_b1    = (const float*)d_in[25];
    const float* bond_w2    = (const float*)d_in[26];
    const float* bond_b2    = (const float*)d_in[27];
    float* out = (float*)d_out;

    int attn_smem = (LSRC * SRC_P + LATD * SRCT_P + 32 * LSRC) * (int)sizeof(float);
    static bool attr_done = false;
    if (!attr_done) {
        cudaFuncSetAttribute(attn_kernel, cudaFuncAttributeMaxDynamicSharedMemorySize, attn_smem);
        cudaFuncSetAttribute(mlp_kernel<512, 1, true>,  cudaFuncAttributeMaxDynamicSharedMemorySize,
                             (64*36 + 256*36 + 64*264 + 64*1 + 128) * (int)sizeof(float));
        cudaFuncSetAttribute(mlp_kernel<512, 40, false>, cudaFuncAttributeMaxDynamicSharedMemorySize,
                             (64*36 + 256*36 + 64*264 + 64*40 + 128) * (int)sizeof(float));
        cudaFuncSetAttribute(mlp_kernel<768, 4, false>,  cudaFuncAttributeMaxDynamicSharedMemorySize,
                             (64*36 + 256*36 + 64*264 + 64*4 + 128) * (int)sizeof(float));
        attr_done = true;
    }

    zero_kernel<<<4, 256>>>();
    hist3_kernel<<<(NBD + 255) / 256, 256>>>(topo_idx, atom_idx, bond_idx);
    scan_kernel<<<3, 256>>>();
    scatter3_kernel<<<(NBD + 255) / 256, 256>>>(topo_idx, atom_idx, bond_idx);

    qproj_kernel<512><<<NT / 64, 256>>>(topo_vecs, A_topo_w, A_topo_b, 0);
    qproj_kernel<512><<<NA / 64, 256>>>(atom_vecs, A_atom_w, A_atom_b, NT);
    qproj_kernel<768><<<NBD / 64, 256>>>(bond_vecs, A_bond_w, A_bond_b, NT + NA);

    attn_kernel<<<dim3(256, 3), 256, attn_smem>>>(src);

    mlp_kernel<512, 1, true><<<NT / 64, 256,
        (64*36 + 256*36 + 64*264 + 64*1 + 128) * (int)sizeof(float)>>>(
        topo_vecs, topo_w1, topo_b1, topo_w2, topo_b2, topo_lab, 0, 0);
    mlp_kernel<512, 40, false><<<NA / 64, 256,
        (64*36 + 256*36 + 64*264 + 64*40 + 128) * (int)sizeof(float)>>>(
        atom_vecs, atom_w1, atom_b1, atom_w2, atom_b2, atom_lab, NT, 1);
    mlp_kernel<768, 4, false><<<NBD / 64, 256,
        (64*36 + 256*36 + 64*264 + 64*4 + 128) * (int)sizeof(float)>>>(
        bond_vecs, bond_w1, bond_b1, bond_w2, bond_b2, bond_lab, NT + NA, 2);

    finalize_kernel<<<1, 1>>>(out);
}

// round 10
// speedup vs baseline: 1.6429x; 1.1200x over previous
#include <cuda_runtime.h>
#include <math.h>

#define NBATCH 256
#define LSRC   400
#define LATD   32
#define NT     38400
#define NA     38400
#define NBD    76800
#define NROWS  (NT + NA + NBD)

#define SRC_P   36    // src_s pitch (floats)
#define SRCT_P  404   // srcT pitch (floats)

typedef unsigned long long u64;

// packed fp32x2 FMA: acc(2 lanes) += a(2 lanes) * b(2 lanes)
__device__ __forceinline__ void ffma2(u64& acc, u64 a, u64 b) {
    asm("fma.rn.f32x2 %0, %1, %2, %0;" : "+l"(acc) : "l"(a), "l"(b));
}
__device__ __forceinline__ float hadd2(u64 p) {
    float2 f = *reinterpret_cast<float2*>(&p);
    return f.x + f.y;
}
// cp.async 16B global->shared
__device__ __forceinline__ void cp_async16(void* smem_dst, const void* gsrc) {
    unsigned s = (unsigned)__cvta_generic_to_shared(smem_dst);
    asm volatile("cp.async.cg.shared.global [%0], [%1], 16;" :: "r"(s), "l"(gsrc));
}
__device__ __forceinline__ void cp_commit() {
    asm volatile("cp.async.commit_group;" ::: "memory");
}
template <int N>
__device__ __forceinline__ void cp_wait() {
    asm volatile("cp.async.wait_group %0;" :: "n"(N) : "memory");
}

// ---------------- scratch (no allocs allowed) ----------------
__device__ __align__(16) float g_q[(size_t)NROWS * LATD];
__device__ __align__(16) float g_cxt[(size_t)NROWS * LATD];
__device__ int          g_order[NROWS];
__device__ int          g_hist[3 * 256];
__device__ int          g_cursor[3 * 256];
__device__ int          g_off[3 * 257];
__device__ double       g_loss[3];
__device__ unsigned int g_corr[3];

// ---------------- setup / sort kernels ----------------
__global__ void zero_kernel() {
    int t = blockIdx.x * blockDim.x + threadIdx.x;
    if (t < 3 * 256) { g_hist[t] = 0; g_cursor[t] = 0; }
    if (t < 3) { g_loss[t] = 0.0; g_corr[t] = 0u; }
}

// privatized histogram: smem counters, one global merge per block
__global__ void __launch_bounds__(256) hist3_kernel(const int* __restrict__ ti,
                                                    const int* __restrict__ ai,
                                                    const int* __restrict__ bi) {
    __shared__ int sh[3 * 256];
    int t = threadIdx.x;
    for (int p = t; p < 3 * 256; p += 256) sh[p] = 0;
    __syncthreads();
    int stride = gridDim.x * blockDim.x;
    for (int i = blockIdx.x * blockDim.x + t; i < NBD; i += stride) {
        if (i < NT)  atomicAdd(&sh[0 * 256 + ti[i]], 1);
        if (i < NA)  atomicAdd(&sh[1 * 256 + ai[i]], 1);
        atomicAdd(&sh[2 * 256 + bi[i]], 1);
    }
    __syncthreads();
    for (int p = t; p < 3 * 256; p += 256) {
        int v = sh[p];
        if (v) atomicAdd(&g_hist[p], v);
    }
}

__global__ void scan_kernel() {
    int head = blockIdx.x;
    int t = threadIdx.x;
    __shared__ int s[256];
    int h = g_hist[head * 256 + t];
    s[t] = h;
    __syncthreads();
    for (int o = 1; o < 256; o <<= 1) {
        int v = (t >= o) ? s[t - o] : 0;
        __syncthreads();
        s[t] += v;
        __syncthreads();
    }
    int excl = s[t] - h;
    g_off[head * 257 + t] = excl;
    g_cursor[head * 256 + t] = excl;
    if (t == 255) g_off[head * 257 + 256] = s[255];
}

__global__ void scatter3_kernel(const int* __restrict__ ti, const int* __restrict__ ai,
                                const int* __restrict__ bi) {
    int i = blockIdx.x * blockDim.x + threadIdx.x;
    if (i < NT) {
        int b = ti[i];
        int pos = atomicAdd(&g_cursor[0 * 256 + b], 1);
        g_order[pos] = i;
    }
    if (i < NA) {
        int b = ai[i];
        int pos = atomicAdd(&g_cursor[1 * 256 + b], 1);
        g_order[NT + pos] = i;
    }
    if (i < NBD) {
        int b = bi[i];
        int pos = atomicAdd(&g_cursor[2 * 256 + b], 1);
        g_order[NT + NA + pos] = i;
    }
}

// ---------------- q projection: cp.async double-buffered, FFMA2 ----------------
// buffer layout (floats): A 64*32 = 2048, W 32*36 = 1152 -> 3200 per buf
#define QP_BUF 3200
template <int D>
__global__ void __launch_bounds__(256) qproj_kernel(const float* __restrict__ vecs,
                                                    const float* __restrict__ Aw,
                                                    const float* __restrict__ Ab,
                                                    int rowbase) {
    __shared__ __align__(16) float sm[2 * QP_BUF];
    int t = threadIdx.x;
    int row0 = blockIdx.x * 64;
    int col = t & 31;
    int rbase = (t >> 5) * 8;
    u64 acc[8];
#pragma unroll
    for (int r = 0; r < 8; r++) acc[r] = 0ull;

    constexpr int NC = D / 32;

    // issue tile loads for chunk `c` into buffer `buf`
    auto load_tile = [&](int buf, int k0) {
        float* A_s = sm + buf * QP_BUF;
        float* W_s = A_s + 2048;
#pragma unroll
        for (int it = 0; it < 2; it++) {
            int m = t + 256 * it;
            int r = m >> 3, kq = m & 7;
            cp_async16(&A_s[r * 32 + 4 * kq],
                       &vecs[(size_t)(row0 + r) * D + k0 + 4 * kq]);
        }
        {
            int c = t >> 3, kq = t & 7;
            cp_async16(&W_s[c * 36 + 4 * kq],
                       &Aw[(size_t)c * D + k0 + 4 * kq]);
        }
        cp_commit();
    };

    load_tile(0, 0);
    for (int c = 0; c < NC; c++) {
        if (c + 1 < NC) { load_tile((c + 1) & 1, (c + 1) * 32); cp_wait<1>(); }
        else            { cp_wait<0>(); }
        __syncthreads();
        const float* A_s = sm + (c & 1) * QP_BUF;
        const float* W_s = A_s + 2048;
#pragma unroll
        for (int kq = 0; kq < 8; kq++) {
            ulonglong2 w4 = *(const ulonglong2*)&W_s[col * 36 + 4 * kq];
#pragma unroll
            for (int r = 0; r < 8; r++) {
                ulonglong2 a4 = *(const ulonglong2*)&A_s[(rbase + r) * 32 + 4 * kq];
                ffma2(acc[r], a4.x, w4.x);
                ffma2(acc[r], a4.y, w4.y);
            }
        }
        __syncthreads();
    }
    float bias = Ab[col];
#pragma unroll
    for (int r = 0; r < 8; r++)
        g_q[(size_t)(rowbase + row0 + rbase + r) * LATD + col] = hadd2(acc[r]) + bias;
}

// ---------------- attention (FFMA2 in scores + weighted sum) ----------------
__global__ void __launch_bounds__(256) attn_kernel(const float* __restrict__ src) {
    extern __shared__ __align__(16) float smem[];
    float* src_s = smem;                          // 400*36
    float* srcT  = smem + LSRC * SRC_P;           // 32*404
    float* att_s = srcT + LATD * SRCT_P;          // 32*400

    int t = threadIdx.x;
    int b = blockIdx.x;
    int head = blockIdx.y;
    int rowbase = (head == 0) ? 0 : ((head == 1) ? NT : (NT + NA));

    for (int m = t; m < LSRC * LATD; m += 256) {
        float v = src[(size_t)b * (LSRC * LATD) + m];
        int l = m >> 5, d = m & 31;
        src_s[l * SRC_P + d] = v;
        srcT[d * SRCT_P + l] = v;
    }
    __syncthreads();

    int w = t >> 5, j = t & 31;
    int start = g_off[head * 257 + b];
    int end   = g_off[head * 257 + b + 1];

    for (int r0 = start + w * 4; r0 < end; r0 += 32) {
        int nr = end - r0; if (nr > 4) nr = 4;

        // ---- scores + softmax, 2 rows at a time ----
#pragma unroll
        for (int pp = 0; pp < 4; pp += 2) {
            int i0 = (pp < nr)     ? g_order[rowbase + r0 + pp]     : g_order[rowbase + r0];
            int i1 = (pp + 1 < nr) ? g_order[rowbase + r0 + pp + 1] : i0;
            u64 q0p[16], q1p[16];
            const ulonglong2* p0 = (const ulonglong2*)&g_q[(size_t)(rowbase + i0) * LATD];
            const ulonglong2* p1 = (const ulonglong2*)&g_q[(size_t)(rowbase + i1) * LATD];
#pragma unroll
            for (int m = 0; m < 8; m++) {
                ulonglong2 v0 = p0[m]; q0p[2 * m] = v0.x; q0p[2 * m + 1] = v0.y;
                ulonglong2 v1 = p1[m]; q1p[2 * m] = v1.x; q1p[2 * m + 1] = v1.y;
            }
            float sv0[13], sv1[13];
#pragma unroll
            for (int tt = 0; tt < 12; tt++) {
                int l = 32 * tt + j;
                const ulonglong2* sp = (const ulonglong2*)&src_s[l * SRC_P];
                u64 s0p = 0ull, s1p = 0ull;
#pragma unroll
                for (int kq = 0; kq < 8; kq++) {
                    ulonglong2 sr = sp[kq];
                    ffma2(s0p, sr.x, q0p[2 * kq]); ffma2(s0p, sr.y, q0p[2 * kq + 1]);
                    ffma2(s1p, sr.x, q1p[2 * kq]); ffma2(s1p, sr.y, q1p[2 * kq + 1]);
                }
                sv0[tt] = hadd2(s0p); sv1[tt] = hadd2(s1p);
            }
            {   // tt = 12 (l = 384 + j, valid iff j < 16)
                int l = 384 + j;
                if (l < LSRC) {
                    const ulonglong2* sp = (const ulonglong2*)&src_s[l * SRC_P];
                    u64 s0p = 0ull, s1p = 0ull;
#pragma unroll
                    for (int kq = 0; kq < 8; kq++) {
                        ulonglong2 sr = sp[kq];
                        ffma2(s0p, sr.x, q0p[2 * kq]); ffma2(s0p, sr.y, q0p[2 * kq + 1]);
                        ffma2(s1p, sr.x, q1p[2 * kq]); ffma2(s1p, sr.y, q1p[2 * kq + 1]);
                    }
                    sv0[12] = hadd2(s0p); sv1[12] = hadd2(s1p);
                } else { sv0[12] = -INFINITY; sv1[12] = -INFINITY; }
            }
            float mx0 = -INFINITY, mx1 = -INFINITY;
#pragma unroll
            for (int tt = 0; tt < 13; tt++) { mx0 = fmaxf(mx0, sv0[tt]); mx1 = fmaxf(mx1, sv1[tt]); }
#pragma unroll
            for (int o = 16; o > 0; o >>= 1) {
                mx0 = fmaxf(mx0, __shfl_xor_sync(0xffffffffu, mx0, o));
                mx1 = fmaxf(mx1, __shfl_xor_sync(0xffffffffu, mx1, o));
            }
            float ss0 = 0.f, ss1 = 0.f;
#pragma unroll
            for (int tt = 0; tt < 13; tt++) {
                float e0 = (sv0[tt] == -INFINITY) ? 0.f : __expf(sv0[tt] - mx0);
                float e1 = (sv1[tt] == -INFINITY) ? 0.f : __expf(sv1[tt] - mx1);
                sv0[tt] = e0; sv1[tt] = e1; ss0 += e0; ss1 += e1;
            }
#pragma unroll
            for (int o = 16; o > 0; o >>= 1) {
                ss0 += __shfl_xor_sync(0xffffffffu, ss0, o);
                ss1 += __shfl_xor_sync(0xffffffffu, ss1, o);
            }
            float inv0 = 1.f / ss0, inv1 = 1.f / ss1;
            float* a0 = &att_s[(w * 4 + pp) * LSRC];
            float* a1 = &att_s[(w * 4 + pp + 1) * LSRC];
#pragma unroll
            for (int tt = 0; tt < 13; tt++) {
                int l = 32 * tt + j;
                if (l < LSRC) { a0[l] = sv0[tt] * inv0; a1[l] = sv1[tt] * inv1; }
            }
        }
        __syncwarp();

        // ---- weighted sum: 4 rows, FFMA2 over l-pairs ----
        u64 c0p = 0ull, c1p = 0ull, c2p = 0ull, c3p = 0ull;
        const ulonglong2* vt = (const ulonglong2*)&srcT[j * SRCT_P];
        const ulonglong2* a0 = (const ulonglong2*)&att_s[(w * 4 + 0) * LSRC];
        const ulonglong2* a1 = (const ulonglong2*)&att_s[(w * 4 + 1) * LSRC];
        const ulonglong2* a2 = (const ulonglong2*)&att_s[(w * 4 + 2) * LSRC];
        const ulonglong2* a3 = (const ulonglong2*)&att_s[(w * 4 + 3) * LSRC];
#pragma unroll 4
        for (int lq = 0; lq < LSRC / 4; lq++) {
            ulonglong2 v  = vt[lq];
            ulonglong2 x0 = a0[lq]; ffma2(c0p, x0.x, v.x); ffma2(c0p, x0.y, v.y);
            ulonglong2 x1 = a1[lq]; ffma2(c1p, x1.x, v.x); ffma2(c1p, x1.y, v.y);
            ulonglong2 x2 = a2[lq]; ffma2(c2p, x2.x, v.x); ffma2(c2p, x2.y, v.y);
            ulonglong2 x3 = a3[lq]; ffma2(c3p, x3.x, v.x); ffma2(c3p, x3.y, v.y);
        }
        float cv[4] = {hadd2(c0p), hadd2(c1p), hadd2(c2p), hadd2(c3p)};
        for (int rr = 0; rr < nr; rr++) {
            int i = g_order[rowbase + r0 + rr];
            g_cxt[(size_t)(rowbase + i) * LATD + j] = cv[rr];
        }
        __syncwarp();
    }
}

// ---------------- fused MLP1 + MLP2 + loss/acc ----------------
// cp.async double-buffered tiles; epilogue h_s/logit_s alias the tile buffers.
// buffer (floats): A 64*36 = 2304, B 256*36 = 9216 -> 11520 per buf, x2 = 23040
#define MLP_BUF 11520
#define MLP_SMEM_FLOATS (2 * MLP_BUF)
#define HP 264
template <int D, int C, bool BCE>
__global__ void __launch_bounds__(256) mlp_kernel(const float* __restrict__ vecs,
                                                  const float* __restrict__ w1,
                                                  const float* __restrict__ b1,
                                                  const float* __restrict__ w2,
                                                  const float* __restrict__ b2,
                                                  const int* __restrict__ labels,
                                                  int rowbase, int head) {
    constexpr int K = D + LATD;
    constexpr int NC = K / 32;
    extern __shared__ __align__(16) float sm[];
    // epilogue aliases (used only after mainloop):
    float* h_s     = sm;                 // 64*HP = 16896
    float* logit_s = sm + 64 * HP;       // 64*C   (16896 + 2560 max = 19456 <= 23040)
    float* red     = logit_s + 64 * C;   // 128

    int t = threadIdx.x;
    int row0 = blockIdx.x * 64;
    int w = t >> 5, j = t & 31;
    u64 acc[8][8];
#pragma unroll
    for (int rr = 0; rr < 8; rr++)
#pragma unroll
        for (int cc = 0; cc < 8; cc++) acc[rr][cc] = 0ull;

    const float* cxt = g_cxt + (size_t)rowbase * LATD;

    auto load_tile = [&](int buf, int k0) {
        float* A_s = sm + buf * MLP_BUF;
        float* B_s = A_s + 2304;
        if (k0 < D) {
#pragma unroll
            for (int it = 0; it < 2; it++) {
                int m = t + 256 * it;
                int r = m >> 3, kq = m & 7;
                cp_async16(&A_s[r * 36 + 4 * kq],
                           &vecs[(size_t)(row0 + r) * D + k0 + 4 * kq]);
            }
        } else {
#pragma unroll
            for (int it = 0; it < 2; it++) {
                int m = t + 256 * it;
                int r = m >> 3, kq = m & 7;
                cp_async16(&A_s[r * 36 + 4 * kq],
                           &cxt[(size_t)(row0 + r) * LATD + 4 * kq]);
            }
        }
#pragma unroll
        for (int it = 0; it < 8; it++) {
            int m = t + 256 * it;
            int c = m >> 3, kq = m & 7;
            cp_async16(&B_s[c * 36 + 4 * kq],
                       &w1[(size_t)c * K + k0 + 4 * kq]);
        }
        cp_commit();
    };

    load_tile(0, 0);
    for (int c = 0; c < NC; c++) {
        if (c + 1 < NC) { load_tile((c + 1) & 1, (c + 1) * 32); cp_wait<1>(); }
        else            { cp_wait<0>(); }
        __syncthreads();
        const float* A_s = sm + (c & 1) * MLP_BUF;
        const float* B_s = A_s + 2304;
#pragma unroll
        for (int kq = 0; kq < 8; kq++) {
            ulonglong2 b4[8];
#pragma unroll
            for (int cc = 0; cc < 8; cc++)
                b4[cc] = *(const ulonglong2*)&B_s[(j + 32 * cc) * 36 + 4 * kq];
#pragma unroll
            for (int rr = 0; rr < 8; rr++) {
                ulonglong2 a4 = *(const ulonglong2*)&A_s[(w * 8 + rr) * 36 + 4 * kq];
#pragma unroll
                for (int cc = 0; cc < 8; cc++) {
                    ffma2(acc[rr][cc], a4.x, b4[cc].x);
                    ffma2(acc[rr][cc], a4.y, b4[cc].y);
                }
            }
        }
        __syncthreads();
    }

    // bias + relu -> h_s (aliases tile buffers; mainloop fully done)
#pragma unroll
    for (int cc = 0; cc < 8; cc++) {
        int c = j + 32 * cc;
        float bias = b1[c];
#pragma unroll
        for (int rr = 0; rr < 8; rr++)
            h_s[(w * 8 + rr) * HP + c] = fmaxf(hadd2(acc[rr][cc]) + bias, 0.f);
    }
    __syncthreads();

    // logits = h @ w2^T + b2 (FFMA2 dots; w2 stays L1/L2-resident across blocks)
    for (int p = t; p < 64 * C; p += 256) {
        int r = p / C, cls = p - r * C;
        const ulonglong2* hp = (const ulonglong2*)&h_s[r * HP];
        const ulonglong2* wp = (const ulonglong2*)&w2[(size_t)cls * 256];
        u64 sp2 = 0ull;
#pragma unroll 8
        for (int kq = 0; kq < 64; kq++) {
            ulonglong2 h4 = hp[kq]; ulonglong2 w4 = wp[kq];
            ffma2(sp2, h4.x, w4.x); ffma2(sp2, h4.y, w4.y);
        }
        logit_s[p] = hadd2(sp2) + b2[cls];
    }
    __syncthreads();

    // per-row loss / accuracy
    if (t < 64) {
        int gi = row0 + t;
        int y = labels[gi];
        float loss;
        int corr;
        if (BCE) {
            float z = logit_s[t];
            float sp = (z > 0.f) ? (z + log1pf(__expf(-z))) : log1pf(__expf(z));
            loss = sp - (float)y * z;
            corr = (((z > 0.f) ? 1 : 0) == y) ? 1 : 0;
        } else {
            float mx = logit_s[t * C];
            int am = 0;
#pragma unroll
            for (int c = 1; c < C; c++) {
                float v = logit_s[t * C + c];
                if (v > mx) { mx = v; am = c; }
            }
            float s = 0.f;
#pragma unroll
            for (int c = 0; c < C; c++) s += __expf(logit_s[t * C + c] - mx);
            loss = logf(s) + mx - logit_s[t * C + y];
            corr = (am == y) ? 1 : 0;
        }
        red[t] = loss;
        ((int*)red)[64 + t] = corr;
    }
    __syncthreads();
    if (t < 32) {
        float L = red[t] + red[t + 32];
        int Ck = ((int*)red)[64 + t] + ((int*)red)[64 + t + 32];
#pragma unroll
        for (int o = 16; o > 0; o >>= 1) {
            L += __shfl_xor_sync(0xffffffffu, L, o);
            Ck += __shfl_xor_sync(0xffffffffu, Ck, o);
        }
        if (t == 0) {
            atomicAdd(&g_loss[head], (double)L);
            atomicAdd(&g_corr[head], (unsigned int)Ck);
        }
    }
}

__global__ void finalize_kernel(float* __restrict__ out) {
    if (threadIdx.x == 0 && blockIdx.x == 0) {
        double L = g_loss[0] + g_loss[1] + g_loss[2];
        out[0] = (float)(L / (double)NBATCH);
        out[1] = (float)g_corr[1] / (float)NA;   // atom_acc
        out[2] = (float)g_corr[0] / (float)NT;   // topo_acc
        out[3] = (float)g_corr[2] / (float)NBD;  // bond_acc
    }
}

// ---------------- launch ----------------
extern "C" void kernel_launch(void* const* d_in, const int* in_sizes, int n_in,
                              void* d_out, int out_size) {
    const float* src        = (const float*)d_in[0];
    const float* topo_vecs  = (const float*)d_in[1];
    const float* atom_vecs  = (const float*)d_in[2];
    const float* bond_vecs  = (const float*)d_in[3];
    const int*   topo_idx   = (const int*)d_in[4];
    const int*   atom_idx   = (const int*)d_in[5];
    const int*   bond_idx   = (const int*)d_in[6];
    const int*   topo_lab   = (const int*)d_in[7];
    const int*   atom_lab   = (const int*)d_in[8];
    const int*   bond_lab   = (const int*)d_in[9];
    const float* A_topo_w   = (const float*)d_in[10];
    const float* A_topo_b   = (const float*)d_in[11];
    const float* A_atom_w   = (const float*)d_in[12];
    const float* A_atom_b   = (const float*)d_in[13];
    const float* A_bond_w   = (const float*)d_in[14];
    const float* A_bond_b   = (const float*)d_in[15];
    const float* topo_w1    = (const float*)d_in[16];
    const float* topo_b1    = (const float*)d_in[17];
    const float* topo_w2    = (const float*)d_in[18];
    const float* topo_b2    = (const float*)d_in[19];
    const float* atom_w1    = (const float*)d_in[20];
    const float* atom_b1    = (const float*)d_in[21];
    const float* atom_w2    = (const float*)d_in[22];
    const float* atom_b2    = (const float*)d_in[23];
    const float* bond_w1    = (const float*)d_in[24];
    const float* bond_b1    = (const float*)d_in[25];
    const float* bond_w2    = (const float*)d_in[26];
    const float* bond_b2    = (const float*)d_in[27];
    float* out = (float*)d_out;

    int attn_smem = (LSRC * SRC_P + LATD * SRCT_P + 32 * LSRC) * (int)sizeof(float);
    int mlp_smem  = MLP_SMEM_FLOATS * (int)sizeof(float);
    static bool attr_done = false;
    if (!attr_done) {
        cudaFuncSetAttribute(attn_kernel, cudaFuncAttributeMaxDynamicSharedMemorySize, attn_smem);
        cudaFuncSetAttribute(mlp_kernel<512, 1, true>,   cudaFuncAttributeMaxDynamicSharedMemorySize, mlp_smem);
        cudaFuncSetAttribute(mlp_kernel<512, 40, false>, cudaFuncAttributeMaxDynamicSharedMemorySize, mlp_smem);
        cudaFuncSetAttribute(mlp_kernel<768, 4, false>,  cudaFuncAttributeMaxDynamicSharedMemorySize, mlp_smem);
        attr_done = true;
    }

    zero_kernel<<<4, 256>>>();
    hist3_kernel<<<64, 256>>>(topo_idx, atom_idx, bond_idx);
    scan_kernel<<<3, 256>>>();
    scatter3_kernel<<<(NBD + 255) / 256, 256>>>(topo_idx, atom_idx, bond_idx);

    qproj_kernel<512><<<NT / 64, 256>>>(topo_vecs, A_topo_w, A_topo_b, 0);
    qproj_kernel<512><<<NA / 64, 256>>>(atom_vecs, A_atom_w, A_atom_b, NT);
    qproj_kernel<768><<<NBD / 64, 256>>>(bond_vecs, A_bond_w, A_bond_b, NT + NA);

    attn_kernel<<<dim3(256, 3), 256, attn_smem>>>(src);

    mlp_kernel<512, 1, true><<<NT / 64, 256, mlp_smem>>>(
        topo_vecs, topo_w1, topo_b1, topo_w2, topo_b2, topo_lab, 0, 0);
    mlp_kernel<512, 40, false><<<NA / 64, 256, mlp_smem>>>(
        atom_vecs, atom_w1, atom_b1, atom_w2, atom_b2, atom_lab, NT, 1);
    mlp_kernel<768, 4, false><<<NBD / 64, 256, mlp_smem>>>(
        bond_vecs, bond_w1, bond_b1, bond_w2, bond_b2, bond_lab, NT + NA, 2);

    finalize_kernel<<<1, 1>>>(out);
}